// round 5
// baseline (speedup 1.0000x reference)
#include <cuda_runtime.h>
#include <math.h>

#define BB    256
#define T2V   1026
#define TP1   1025
#define SSV   1024
#define NVOC  35
#define H7    224
#define HN    (BB*SSV)
#define EPSV  2.220446049250313e-16f
#define LOG2E 1.4426950408889634f
#define LN2   0.6931471805599453f
#define FULLM 0xffffffffu

// ---------------- device scratch ----------------
static __device__ float g_prex[NVOC * H7];
static __device__ float g_c [BB * TP1 * 32];
static __device__ float g_cb[BB * TP1 * 32];
static __device__ float g_d [BB * TP1 * 32];   // delta in log2 domain
static __device__ float g_o [BB * TP1 * 32];
static __device__ float g_h [BB * TP1 * 32];
static __device__ float g_loglam[BB], g_nev[BB], g_integ[BB];

// ---------------- fast math ----------------
__device__ __forceinline__ float ex2f(float x){ float r; asm("ex2.approx.f32 %0,%1;":"=f"(r):"f"(x)); return r; }
__device__ __forceinline__ float lg2f(float x){ float r; asm("lg2.approx.f32 %0,%1;":"=f"(r):"f"(x)); return r; }
__device__ __forceinline__ float rcpf(float x){ float r; asm("rcp.approx.f32 %0,%1;":"=f"(r):"f"(x)); return r; }
__device__ __forceinline__ float tanh_fast(float x){
    float s2 = ex2f(-2.0f * LOG2E * fabsf(x));
    float tv = (1.0f - s2) * rcpf(1.0f + s2);
    return x >= 0.0f ? tv : -tv;
}
__device__ __forceinline__ float softplus_fast(float x){
    return fmaxf(x, 0.0f) + lg2f(1.0f + ex2f(-fabsf(x) * LOG2E)) * LN2;
}

// block reduction (result valid on thread 0); blockDim = 256
__device__ __forceinline__ float block_reduce(float v, float* sh) {
    #pragma unroll
    for (int o = 16; o > 0; o >>= 1) v += __shfl_down_sync(FULLM, v, o);
    int wid = threadIdx.x >> 5, lid = threadIdx.x & 31;
    if (lid == 0) sh[wid] = v;
    __syncthreads();
    if (wid == 0) {
        v = (lid < 8) ? sh[lid] : 0.0f;
        #pragma unroll
        for (int o = 4; o > 0; o >>= 1) v += __shfl_down_sync(FULLM, v, o);
    }
    return v;
}

// ---------------- kernel A: prex[v][j] = Emb[v]·Wx[:,j] + b[j] ------------
__global__ void k_prex(const float* __restrict__ Emb,
                       const float* __restrict__ W,
                       const float* __restrict__ bias) {
    int v = blockIdx.x;
    int j = threadIdx.x;
    float acc = bias[j];
    #pragma unroll
    for (int k = 0; k < 32; k++)
        acc += Emb[v * 32 + k] * W[k * H7 + j];
    g_prex[v * H7 + j] = acc;
}

// ---------------- kernel B: scan, one CTA/batch, ONE barrier per step -----
// warp w owns hidden units 4w..4w+3 and ALL their 7 gates:
//   lane l = 7q+g (l<28) computes gate g of unit 4w+q  (column j=32g+4w+q)
// phase 2 is intra-warp (lanes 0..3), so only one __syncthreads per step.
__global__ void __launch_bounds__(256, 2)
k_scan(const int*   __restrict__ event,
       const float* __restrict__ dtime,
       const float* __restrict__ W) {
    const int b    = blockIdx.x;
    const int tid  = threadIdx.x;
    const int w    = tid >> 5;
    const int lane = tid & 31;
    const int q    = lane / 7;        // unit-within-warp (l<28)
    const int g    = lane % 7;        // gate id
    const bool on  = (lane < 28);
    const int  j   = on ? (32 * g + 4 * w + q) : 0;

    __shared__ float4 h4s[8];                    // h vector (32 floats)
    __shared__ float  act_s[8][28];
    float* h_sh = (float*)h4s;

    // per-lane weight column (rows 32..63 of W = W_h)
    float wcol[32];
    #pragma unroll
    for (int k = 0; k < 32; k++) wcol[k] = W[(32 + k) * H7 + j];

    const int*   evrow = event + b * T2V;
    const float* dtrow = dtime + b * T2V;

    if (tid < 32) h_sh[tid] = 0.0f;

    float cm = 0.0f, cbm = 0.0f;                 // carries, lanes 0..3
    int   ev  = evrow[0];
    float px  = g_prex[ev * H7 + j];             // prefetched pre-x term
    float dtn = dtrow[1];

    float* outc  = g_c  + b * TP1 * 32;
    float* outcb = g_cb + b * TP1 * 32;
    float* outd  = g_d  + b * TP1 * 32;
    float* outo  = g_o  + b * TP1 * 32;
    float* outh  = g_h  + b * TP1 * 32;

    __syncthreads();

    for (int t = 0; t < TP1; t++) {
        // ---------- phase 1: 28 pre-activations per warp ----------
        if (on) {
            float a0 = px, a1 = 0.f, a2 = 0.f, a3 = 0.f;
            #pragma unroll
            for (int p = 0; p < 8; p++) {
                float4 hv = h4s[p];              // broadcast LDS.128
                a0 = fmaf(hv.x, wcol[4 * p + 0], a0);
                a1 = fmaf(hv.y, wcol[4 * p + 1], a1);
                a2 = fmaf(hv.z, wcol[4 * p + 2], a2);
                a3 = fmaf(hv.w, wcol[4 * p + 3], a3);
            }
            float pre = (a0 + a1) + (a2 + a3);

            // activations from one ex2 + one rcp (+ predicated lg2)
            float ax = fabsf(pre);
            float s  = ex2f(-ax * LOG2E);
            float a;
            if (g == 2) {                         // tanh(z)
                float s2 = s * s;
                float tv = (1.0f - s2) * rcpf(1.0f + s2);
                a = (pre >= 0.0f) ? tv : -tv;
            } else if (g == 6) {                  // softplus/ln2 (log2 domain)
                a = fmaxf(pre, 0.0f) * LOG2E + lg2f(1.0f + s);
            } else {                              // sigmoid
                float r = rcpf(1.0f + s);
                a = (pre >= 0.0f) ? r : s * r;
            }
            act_s[w][lane] = a;
        }
        // prefetch next step's token + pre-x (off critical path)
        if (t + 1 < TP1) {
            ev = evrow[t + 1];
            px = g_prex[ev * H7 + j];
        }
        __syncwarp();

        // ---------- phase 2: intra-warp cell update (lanes 0..3) ----------
        if (lane < 4) {
            const float* A = act_s[w];
            float iv  = A[7 * lane + 0];
            float fv  = A[7 * lane + 1];
            float zv  = A[7 * lane + 2];
            float ov  = A[7 * lane + 3];
            float ibv = A[7 * lane + 4];
            float fbv = A[7 * lane + 5];
            float L   = A[7 * lane + 6];

            float c  = fmaf(fv,  cm,  iv  * zv);
            float cb = fmaf(fbv, cbm, ibv * zv);
            float e  = ex2f(-L * dtn);
            float cn = fmaf(c - cb, e, cb);
            float h  = ov * tanh_fast(cn);

            int u = 4 * w + lane;
            int base = t * 32 + u;
            outc [base] = c;
            outcb[base] = cb;
            outd [base] = L;
            outo [base] = ov;
            outh [base] = h;

            h_sh[u] = h;
            cm = cn; cbm = cb;
            int ti = t + 2; if (ti > TP1) ti = TP1;
            dtn = dtrow[ti];
        }
        __syncthreads();
    }
}

// ---------------- kernel C: MC sampling + lambda_sample + integral ---------
__global__ void __launch_bounds__(256)
k_sample(const float* __restrict__ dts,
         const float* __restrict__ mask,
         const float* __restrict__ dur,
         const float* __restrict__ Wl,
         float* __restrict__ lam_out) {
    const int b    = blockIdx.x;
    const int tid  = threadIdx.x;
    const int lane = tid & 31;
    const int wid  = tid >> 5;

    __shared__ float sh_ch[8][32];
    __shared__ float red[8];

    float wle[32];
    const float4* wl4 = (const float4*)(Wl + lane * 32);
    #pragma unroll
    for (int p = 0; p < 8; p++) {
        float4 wv = wl4[p];
        wle[4 * p + 0] = wv.x; wle[4 * p + 1] = wv.y;
        wle[4 * p + 2] = wv.z; wle[4 * p + 3] = wv.w;
    }

    float accLam = 0.0f, accMask = 0.0f;

    for (int s = wid; s < SSV; s += 8) {
        int r    = b * SSV + s;
        int base = r * 32;

        float cv  = g_c [base + lane];
        float cbv = g_cb[base + lane];
        float dv  = g_d [base + lane];    // log2-domain delta
        float ov  = g_o [base + lane];
        float dtv = dts[r];

        float cd  = fmaf(cv - cbv, ex2f(-dv * dtv), cbv);
        float chv = ov * tanh_fast(cd);
        sh_ch[wid][lane] = chv;
        __syncwarp();

        float d0 = 0.f, d1 = 0.f, d2 = 0.f, d3 = 0.f;
        const float4* ch4 = (const float4*)sh_ch[wid];
        #pragma unroll
        for (int p = 0; p < 8; p++) {
            float4 c4 = ch4[p];
            d0 = fmaf(c4.x, wle[4 * p + 0], d0);
            d1 = fmaf(c4.y, wle[4 * p + 1], d1);
            d2 = fmaf(c4.z, wle[4 * p + 2], d2);
            d3 = fmaf(c4.w, wle[4 * p + 3], d3);
        }
        float sp = softplus_fast((d0 + d1) + (d2 + d3));
        lam_out[(size_t)r * 32 + lane] = sp;

        float m = mask[r];
        accLam += sp * m;
        if (lane == 0) accMask += m;
        __syncwarp();
    }

    float sLam = block_reduce(accLam, red);
    __syncthreads();
    float sMask = block_reduce(accMask, red);
    if (tid == 0) g_integ[b] = __fdividef(sLam, sMask) * dur[b];
}

// ---------------- kernel D: target log-lambda (padded SMEM, no conflicts) --
__global__ void __launch_bounds__(256)
k_target(const int* __restrict__ event,
         const float* __restrict__ Wl) {
    const int b   = blockIdx.x;
    const int tid = threadIdx.x;

    __shared__ float wl[32 * 33];              // stride 33: conflict-free
    __shared__ float red[8];
    for (int i = tid; i < 1024; i += 256)
        wl[(i >> 5) * 33 + (i & 31)] = Wl[i];
    __syncthreads();

    const int* evrow = event + b * T2V;
    float accL = 0.0f, accN = 0.0f;

    for (int t = tid; t < TP1; t += 256) {
        int tgt = evrow[t + 1];
        bool m  = (tgt < 32);
        int tt  = m ? tgt : 0;

        const float4* h4 = (const float4*)(g_h + (b * TP1 + t) * 32);
        const float* wr  = wl + tt * 33;
        float d0 = 0.f, d1 = 0.f, d2 = 0.f, d3 = 0.f;
        #pragma unroll
        for (int p = 0; p < 8; p++) {
            float4 hv = h4[p];
            d0 = fmaf(hv.x, wr[4 * p + 0], d0);
            d1 = fmaf(hv.y, wr[4 * p + 1], d1);
            d2 = fmaf(hv.z, wr[4 * p + 2], d2);
            d3 = fmaf(hv.w, wr[4 * p + 3], d3);
        }
        float lam = softplus_fast((d0 + d1) + (d2 + d3));
        if (m) { accL += lg2f(lam + EPSV) * LN2; accN += 1.0f; }
    }

    float sL = block_reduce(accL, red);
    __syncthreads();
    float sN = block_reduce(accN, red);
    if (tid == 0) { g_loglam[b] = sL; g_nev[b] = sN; }
}

// ---------------- kernel E: final scalars ----------------------------------
__global__ void __launch_bounds__(256)
k_final(float* __restrict__ out) {
    const int tid = threadIdx.x;
    __shared__ float red[8];
    float lp = g_loglam[tid] - g_integ[tid];
    float nv = g_nev[tid];
    float sLP = block_reduce(lp, red);
    __syncthreads();
    float sNV = block_reduce(nv, red);
    if (tid == 0) {
        out[0] = -sLP;
        out[1] = sNV;
    }
}

// ---------------- launch ----------------
extern "C" void kernel_launch(void* const* d_in, const int* in_sizes, int n_in,
                              void* d_out, int out_size) {
    const int*   event = (const int*)  d_in[0];
    const float* dtime = (const float*)d_in[1];
    const float* dur   = (const float*)d_in[2];
    const float* dts   = (const float*)d_in[3];
    // d_in[4] = index_of_hidden_sampling (unused by the reference)
    const float* mask  = (const float*)d_in[5];
    const float* Emb   = (const float*)d_in[6];
    const float* W     = (const float*)d_in[7];
    const float* bias  = (const float*)d_in[8];
    const float* Wl    = (const float*)d_in[9];

    float* out = (float*)d_out;
    long long lam_elems = (long long)HN * 32;
    long long lamoff = (long long)out_size - lam_elems;
    if (lamoff < 0) lamoff = 0;
    float* lam_out = out + lamoff;

    k_prex  <<<NVOC, H7>>>(Emb, W, bias);
    k_scan  <<<BB, 256>>>(event, dtime, W);
    k_sample<<<BB, 256>>>(dts, mask, dur, Wl, lam_out);
    k_target<<<BB, 256>>>(event, Wl);
    k_final <<<1, 256>>>(out);
}

// round 6
// speedup vs baseline: 1.0606x; 1.0606x over previous
#include <cuda_runtime.h>
#include <math.h>

#define BB    256
#define T2V   1026
#define TP1   1025
#define SSV   1024
#define NVOC  35
#define H7    224
#define HN    (BB*SSV)
#define EPSV  2.220446049250313e-16f
#define LOG2E 1.4426950408889634f
#define LN2   0.6931471805599453f
#define FULLM 0xffffffffu

// ---------------- device scratch ----------------
static __device__ float g_prex[NVOC * H7];     // permuted layout (see k_prex)
static __device__ float g_c [BB * TP1 * 32];
static __device__ float g_cb[BB * TP1 * 32];
static __device__ float g_d [BB * TP1 * 32];   // delta in log2 domain
static __device__ float g_o [BB * TP1 * 32];
static __device__ float g_h [BB * TP1 * 32];
static __device__ float g_loglam[BB], g_nev[BB], g_integ[BB];

// ---------------- fast math ----------------
__device__ __forceinline__ float ex2f(float x){ float r; asm("ex2.approx.f32 %0,%1;":"=f"(r):"f"(x)); return r; }
__device__ __forceinline__ float lg2f(float x){ float r; asm("lg2.approx.f32 %0,%1;":"=f"(r):"f"(x)); return r; }
__device__ __forceinline__ float rcpf(float x){ float r; asm("rcp.approx.f32 %0,%1;":"=f"(r):"f"(x)); return r; }
__device__ __forceinline__ float tanh_fast(float x){
    float s2 = ex2f(-2.0f * LOG2E * fabsf(x));
    float tv = (1.0f - s2) * rcpf(1.0f + s2);
    return x >= 0.0f ? tv : -tv;
}
__device__ __forceinline__ float softplus_fast(float x){
    return fmaxf(x, 0.0f) + lg2f(1.0f + ex2f(-fabsf(x) * LOG2E)) * LN2;
}

// block reduction (result valid on thread 0); blockDim = 256
__device__ __forceinline__ float block_reduce(float v, float* sh) {
    #pragma unroll
    for (int o = 16; o > 0; o >>= 1) v += __shfl_down_sync(FULLM, v, o);
    int wid = threadIdx.x >> 5, lid = threadIdx.x & 31;
    if (lid == 0) sh[wid] = v;
    __syncthreads();
    if (wid == 0) {
        v = (lid < 8) ? sh[lid] : 0.0f;
        #pragma unroll
        for (int o = 4; o > 0; o >>= 1) v += __shfl_down_sync(FULLM, v, o);
    }
    return v;
}

// ---------------- kernel A: prex (permuted) --------------------------------
// scan lane mapping: warp w, lane l=7q+g (l<28) handles gate g of unit u=4w+q,
// i.e. original column j = 32g + 4w + q.  prex stored at slot = w*28 + l so
// the scan's SMEM read is dense & conflict-free.
__global__ void k_prex(const float* __restrict__ Emb,
                       const float* __restrict__ W,
                       const float* __restrict__ bias) {
    int v = blockIdx.x;
    int j = threadIdx.x;                       // 0..223 original column
    float acc = bias[j];
    #pragma unroll
    for (int k = 0; k < 32; k++)
        acc += Emb[v * 32 + k] * W[k * H7 + j];
    int g = j >> 5, u = j & 31, w = u >> 2, q = u & 3;
    g_prex[v * H7 + (w * 28 + 7 * q + g)] = acc;
}

// ---------------- kernel B: scan, ONE barrier per step ---------------------
__global__ void __launch_bounds__(256, 2)
k_scan(const int*   __restrict__ event,
       const float* __restrict__ dtime,
       const float* __restrict__ W) {
    const int b    = blockIdx.x;
    const int tid  = threadIdx.x;
    const int w    = tid >> 5;
    const int lane = tid & 31;
    const int q    = lane / 7;
    const int g    = lane % 7;
    const bool on  = (lane < 28);
    const int  u   = 4 * w + q;                 // hidden unit (on lanes)
    const int  j   = on ? (32 * g + u) : 0;     // original column
    const int  slot = w * 28 + lane;            // permuted prex slot (on lanes)

    __shared__ float  prex_sh[NVOC * H7];       // 31.4 KB
    __shared__ float4 h4s[8];                   // h vector
    __shared__ float  act_s[8][28];
    __shared__ float  acte_s[8][4];             // precomputed decay e
    __shared__ float  ringb[5][16][32];         // c,cb,L,o,h staging (16 slots)
    __shared__ float  dt_sh[T2V];
    __shared__ int    ev_sh[T2V];

    float* h_sh = (float*)h4s;

    const int*   evrow = event + b * T2V;
    const float* dtrow = dtime + b * T2V;
    for (int i = tid; i < NVOC * H7; i += 256) prex_sh[i] = g_prex[i];
    for (int i = tid; i < T2V; i += 256) { dt_sh[i] = dtrow[i]; ev_sh[i] = evrow[i]; }

    float wcol[32];
    #pragma unroll
    for (int k = 0; k < 32; k++) wcol[k] = W[(32 + k) * H7 + j];

    if (tid < 32) h_sh[tid] = 0.0f;
    float cm = 0.0f, cbm = 0.0f;                // carries (lanes 0..3)

    float* outc  = g_c  + b * TP1 * 32;
    float* outcb = g_cb + b * TP1 * 32;
    float* outd  = g_d  + b * TP1 * 32;
    float* outo  = g_o  + b * TP1 * 32;
    float* outh  = g_h  + b * TP1 * 32;

    __syncthreads();

    float px   = on ? prex_sh[ev_sh[0] * H7 + slot] : 0.0f;
    float dt_c = dt_sh[1];                      // dt for step 0

    for (int t = 0; t < TP1; t++) {
        // ---------- periodic coalesced flush (off dependency path) --------
        if ((t & 7) == 0 && t > 0) {
            int ts = t - 8 + w;                 // warp w flushes step ts
            int sl = ts & 15;
            int gbase = ts * 32 + lane;
            outc [gbase] = ringb[0][sl][lane];
            outcb[gbase] = ringb[1][sl][lane];
            outd [gbase] = ringb[2][sl][lane];
            outo [gbase] = ringb[3][sl][lane];
            outh [gbase] = ringb[4][sl][lane];
        }

        // ---------- phase 1: 28 pre-activations per warp -------------------
        if (on) {
            float a0 = px, a1 = 0.f, a2 = 0.f, a3 = 0.f;
            #pragma unroll
            for (int p = 0; p < 8; p++) {
                float4 hv = h4s[p];             // broadcast LDS.128
                a0 = fmaf(hv.x, wcol[4 * p + 0], a0);
                a1 = fmaf(hv.y, wcol[4 * p + 1], a1);
                a2 = fmaf(hv.z, wcol[4 * p + 2], a2);
                a3 = fmaf(hv.w, wcol[4 * p + 3], a3);
            }
            float pre = (a0 + a1) + (a2 + a3);

            float ax = fabsf(pre);
            float s  = ex2f(-ax * LOG2E);
            float a;
            if (g == 2) {                        // tanh(z)
                float s2 = s * s;
                float tv = (1.0f - s2) * rcpf(1.0f + s2);
                a = (pre >= 0.0f) ? tv : -tv;
            } else if (g == 6) {                 // softplus/ln2 (log2 domain)
                a = fmaxf(pre, 0.0f) * LOG2E + lg2f(1.0f + s);
                acte_s[w][q] = ex2f(-a * dt_c);  // decay for THIS step
            } else {                             // sigmoid
                float r = rcpf(1.0f + s);
                a = (pre >= 0.0f) ? r : s * r;
            }
            act_s[w][lane] = a;

            // prefetch next step's pre-x + dt (hidden under phase 2+barrier)
            int tn = (t + 1 < TP1) ? t + 1 : t;
            px   = prex_sh[ev_sh[tn] * H7 + slot];
            dt_c = dt_sh[tn + 1];
        }
        __syncwarp();

        // ---------- phase 2: intra-warp cell update (lanes 0..3) -----------
        if (lane < 4) {
            const float* A = act_s[w];
            float iv  = A[7 * lane + 0];
            float fv  = A[7 * lane + 1];
            float zv  = A[7 * lane + 2];
            float ov  = A[7 * lane + 3];
            float ibv = A[7 * lane + 4];
            float fbv = A[7 * lane + 5];
            float L   = A[7 * lane + 6];
            float e   = acte_s[w][lane];

            float c  = fmaf(fv,  cm,  iv  * zv);
            float cb = fmaf(fbv, cbm, ibv * zv);
            float cn = fmaf(c - cb, e, cb);
            float h  = ov * tanh_fast(cn);

            int sl = t & 15;
            int uu = 4 * w + lane;
            ringb[0][sl][uu] = c;
            ringb[1][sl][uu] = cb;
            ringb[2][sl][uu] = L;
            ringb[3][sl][uu] = ov;
            ringb[4][sl][uu] = h;

            h_sh[uu] = h;
            cm = cn; cbm = cb;
        }
        __syncthreads();
    }

    // tail flush: steps not covered by the last in-loop flush (1024)
    if (w < (TP1 & 7)) {
        int ts = (TP1 & ~7) + w;
        int sl = ts & 15;
        int gbase = ts * 32 + lane;
        outc [gbase] = ringb[0][sl][lane];
        outcb[gbase] = ringb[1][sl][lane];
        outd [gbase] = ringb[2][sl][lane];
        outo [gbase] = ringb[3][sl][lane];
        outh [gbase] = ringb[4][sl][lane];
    }
}

// ---------------- kernel C: MC sampling + lambda_sample + integral ---------
__global__ void __launch_bounds__(256)
k_sample(const float* __restrict__ dts,
         const float* __restrict__ mask,
         const float* __restrict__ dur,
         const float* __restrict__ Wl,
         float* __restrict__ lam_out) {
    const int b    = blockIdx.x;
    const int tid  = threadIdx.x;
    const int lane = tid & 31;
    const int wid  = tid >> 5;

    __shared__ float sh_ch[8][32];
    __shared__ float red[8];

    float wle[32];
    const float4* wl4 = (const float4*)(Wl + lane * 32);
    #pragma unroll
    for (int p = 0; p < 8; p++) {
        float4 wv = wl4[p];
        wle[4 * p + 0] = wv.x; wle[4 * p + 1] = wv.y;
        wle[4 * p + 2] = wv.z; wle[4 * p + 3] = wv.w;
    }

    float accLam = 0.0f, accMask = 0.0f;

    for (int s = wid; s < SSV; s += 8) {
        int r    = b * SSV + s;
        int base = r * 32;

        float cv  = g_c [base + lane];
        float cbv = g_cb[base + lane];
        float dv  = g_d [base + lane];    // log2-domain delta
        float ov  = g_o [base + lane];
        float dtv = dts[r];

        float cd  = fmaf(cv - cbv, ex2f(-dv * dtv), cbv);
        float chv = ov * tanh_fast(cd);
        sh_ch[wid][lane] = chv;
        __syncwarp();

        float d0 = 0.f, d1 = 0.f, d2 = 0.f, d3 = 0.f;
        const float4* ch4 = (const float4*)sh_ch[wid];
        #pragma unroll
        for (int p = 0; p < 8; p++) {
            float4 c4 = ch4[p];
            d0 = fmaf(c4.x, wle[4 * p + 0], d0);
            d1 = fmaf(c4.y, wle[4 * p + 1], d1);
            d2 = fmaf(c4.z, wle[4 * p + 2], d2);
            d3 = fmaf(c4.w, wle[4 * p + 3], d3);
        }
        float sp = softplus_fast((d0 + d1) + (d2 + d3));
        lam_out[(size_t)r * 32 + lane] = sp;

        float m = mask[r];
        accLam += sp * m;
        if (lane == 0) accMask += m;
        __syncwarp();
    }

    float sLam = block_reduce(accLam, red);
    __syncthreads();
    float sMask = block_reduce(accMask, red);
    if (tid == 0) g_integ[b] = __fdividef(sLam, sMask) * dur[b];
}

// ---------------- kernel D: target log-lambda ------------------------------
__global__ void __launch_bounds__(256)
k_target(const int* __restrict__ event,
         const float* __restrict__ Wl) {
    const int b   = blockIdx.x;
    const int tid = threadIdx.x;

    __shared__ float wl[32 * 33];              // stride 33: conflict-free
    __shared__ float red[8];
    for (int i = tid; i < 1024; i += 256)
        wl[(i >> 5) * 33 + (i & 31)] = Wl[i];
    __syncthreads();

    const int* evrow = event + b * T2V;
    float accL = 0.0f, accN = 0.0f;

    for (int t = tid; t < TP1; t += 256) {
        int tgt = evrow[t + 1];
        bool m  = (tgt < 32);
        int tt  = m ? tgt : 0;

        const float4* h4 = (const float4*)(g_h + (b * TP1 + t) * 32);
        const float* wr  = wl + tt * 33;
        float d0 = 0.f, d1 = 0.f, d2 = 0.f, d3 = 0.f;
        #pragma unroll
        for (int p = 0; p < 8; p++) {
            float4 hv = h4[p];
            d0 = fmaf(hv.x, wr[4 * p + 0], d0);
            d1 = fmaf(hv.y, wr[4 * p + 1], d1);
            d2 = fmaf(hv.z, wr[4 * p + 2], d2);
            d3 = fmaf(hv.w, wr[4 * p + 3], d3);
        }
        float lam = softplus_fast((d0 + d1) + (d2 + d3));
        if (m) { accL += lg2f(lam + EPSV) * LN2; accN += 1.0f; }
    }

    float sL = block_reduce(accL, red);
    __syncthreads();
    float sN = block_reduce(accN, red);
    if (tid == 0) { g_loglam[b] = sL; g_nev[b] = sN; }
}

// ---------------- kernel E: final scalars ----------------------------------
__global__ void __launch_bounds__(256)
k_final(float* __restrict__ out) {
    const int tid = threadIdx.x;
    __shared__ float red[8];
    float lp = g_loglam[tid] - g_integ[tid];
    float nv = g_nev[tid];
    float sLP = block_reduce(lp, red);
    __syncthreads();
    float sNV = block_reduce(nv, red);
    if (tid == 0) {
        out[0] = -sLP;
        out[1] = sNV;
    }
}

// ---------------- launch ----------------
extern "C" void kernel_launch(void* const* d_in, const int* in_sizes, int n_in,
                              void* d_out, int out_size) {
    const int*   event = (const int*)  d_in[0];
    const float* dtime = (const float*)d_in[1];
    const float* dur   = (const float*)d_in[2];
    const float* dts   = (const float*)d_in[3];
    // d_in[4] = index_of_hidden_sampling (unused by the reference)
    const float* mask  = (const float*)d_in[5];
    const float* Emb   = (const float*)d_in[6];
    const float* W     = (const float*)d_in[7];
    const float* bias  = (const float*)d_in[8];
    const float* Wl    = (const float*)d_in[9];

    float* out = (float*)d_out;
    long long lam_elems = (long long)HN * 32;
    long long lamoff = (long long)out_size - lam_elems;
    if (lamoff < 0) lamoff = 0;
    float* lam_out = out + lamoff;

    k_prex  <<<NVOC, H7>>>(Emb, W, bias);
    k_scan  <<<BB, 256>>>(event, dtime, W);
    k_sample<<<BB, 256>>>(dts, mask, dur, Wl, lam_out);
    k_target<<<BB, 256>>>(event, Wl);
    k_final <<<1, 256>>>(out);
}

// round 7
// speedup vs baseline: 1.3382x; 1.2617x over previous
#include <cuda_runtime.h>
#include <math.h>

#define BB    256
#define T2V   1026
#define TP1   1025
#define SSV   1024
#define NVOC  35
#define H7    224
#define HN    (BB*SSV)
#define EPSV  2.220446049250313e-16f
#define LOG2E 1.4426950408889634f
#define LN2   0.6931471805599453f
#define FULLM 0xffffffffu

// ---------------- device scratch ----------------
static __device__ float g_prex[NVOC * H7];
static __device__ float g_c [BB * TP1 * 32];
static __device__ float g_cb[BB * TP1 * 32];
static __device__ float g_d [BB * TP1 * 32];   // delta in log2 domain
static __device__ float g_o [BB * TP1 * 32];
static __device__ float g_h [BB * TP1 * 32];
static __device__ float g_loglam[BB], g_nev[BB], g_integ[BB];

// ---------------- fast math ----------------
__device__ __forceinline__ float ex2f(float x){ float r; asm("ex2.approx.f32 %0,%1;":"=f"(r):"f"(x)); return r; }
__device__ __forceinline__ float lg2f(float x){ float r; asm("lg2.approx.f32 %0,%1;":"=f"(r):"f"(x)); return r; }
__device__ __forceinline__ float rcpf(float x){ float r; asm("rcp.approx.f32 %0,%1;":"=f"(r):"f"(x)); return r; }
__device__ __forceinline__ float sig_fast(float x){
    float s = ex2f(-fabsf(x) * LOG2E);
    float r = rcpf(1.0f + s);
    return x >= 0.0f ? r : s * r;
}
__device__ __forceinline__ float tanh_fast(float x){
    float s2 = ex2f(-2.0f * LOG2E * fabsf(x));
    float tv = (1.0f - s2) * rcpf(1.0f + s2);
    return x >= 0.0f ? tv : -tv;
}
__device__ __forceinline__ float softplus_fast(float x){
    return fmaxf(x, 0.0f) + lg2f(1.0f + ex2f(-fabsf(x) * LOG2E)) * LN2;
}
__device__ __forceinline__ float softplus_log2(float x){   // softplus(x)/ln2
    return fmaxf(x, 0.0f) * LOG2E + lg2f(1.0f + ex2f(-fabsf(x) * LOG2E));
}
__device__ __forceinline__ unsigned su32(const void* p){
    unsigned a;
    asm("{ .reg .u64 t; cvta.to.shared.u64 t, %1; cvt.u32.u64 %0, t; }" : "=r"(a) : "l"(p));
    return a;
}

// block reduction (result valid on thread 0); blockDim = 256
__device__ __forceinline__ float block_reduce(float v, float* sh) {
    #pragma unroll
    for (int o = 16; o > 0; o >>= 1) v += __shfl_down_sync(FULLM, v, o);
    int wid = threadIdx.x >> 5, lid = threadIdx.x & 31;
    if (lid == 0) sh[wid] = v;
    __syncthreads();
    if (wid == 0) {
        v = (lid < 8) ? sh[lid] : 0.0f;
        #pragma unroll
        for (int o = 4; o > 0; o >>= 1) v += __shfl_down_sync(FULLM, v, o);
    }
    return v;
}

// ---------------- kernel A: prex[v][j] = Emb[v]·Wx[:,j] + b[j] -------------
__global__ void k_prex(const float* __restrict__ Emb,
                       const float* __restrict__ W,
                       const float* __restrict__ bias) {
    int v = blockIdx.x;
    int j = threadIdx.x;
    float acc = bias[j];
    #pragma unroll
    for (int k = 0; k < 32; k++)
        acc += Emb[v * 32 + k] * W[k * H7 + j];
    g_prex[v * H7 + j] = acc;
}

// ---------------- kernel B: scan, TWO batches per CTA, packed f32x2 dots ---
// thread j (0..223) = gate (j>>5) of unit (j&31); uniform activation per warp.
// phase2: warp0 updates batch A, warp1 updates batch B.
__global__ void __launch_bounds__(224, 1)
k_scan(const int*   __restrict__ event,
       const float* __restrict__ dtime,
       const float* __restrict__ W) {
    const int cb   = blockIdx.x;            // 0..127
    const int b0   = 2 * cb, b1 = 2 * cb + 1;
    const int j    = threadIdx.x;
    const int w    = j >> 5;
    const int lane = j & 31;

    __shared__ float  prex_sh[NVOC * H7];   // 31.4 KB
    __shared__ float  act[2][H7];
    __shared__ float  e_sh[2][32];
    __shared__ float2 h2s[2][16];           // h vectors, float2-aligned
    __shared__ float  dt_sh[2][T2V];
    __shared__ int    ev_sh[2][T2V];

    for (int i = j; i < NVOC * H7; i += 224) prex_sh[i] = g_prex[i];
    for (int i = j; i < T2V; i += 224) {
        dt_sh[0][i] = dtime[b0 * T2V + i];
        dt_sh[1][i] = dtime[b1 * T2V + i];
        ev_sh[0][i] = event[b0 * T2V + i];
        ev_sh[1][i] = event[b1 * T2V + i];
    }

    // packed recurrent weight column: wp[k] = (W_h[2k][j], W_h[2k+1][j])
    unsigned long long wp[16];
    #pragma unroll
    for (int k = 0; k < 16; k++) {
        float wlo = W[(32 + 2 * k)     * H7 + j];
        float whi = W[(32 + 2 * k + 1) * H7 + j];
        asm("mov.b64 %0, {%1,%2};" : "=l"(wp[k]) : "f"(wlo), "f"(whi));
    }

    if (j < 64) ((float*)h2s)[j] = 0.0f;
    float cm = 0.0f, cbm = 0.0f;            // carries: warp0→A, warp1→B

    const unsigned hbA = su32(&h2s[0][0]);
    const unsigned hbB = su32(&h2s[1][0]);

    float* outcA  = g_c  + b0 * TP1 * 32;  float* outcB  = g_c  + b1 * TP1 * 32;
    float* outcbA = g_cb + b0 * TP1 * 32;  float* outcbB = g_cb + b1 * TP1 * 32;
    float* outdA  = g_d  + b0 * TP1 * 32;  float* outdB  = g_d  + b1 * TP1 * 32;
    float* outoA  = g_o  + b0 * TP1 * 32;  float* outoB  = g_o  + b1 * TP1 * 32;
    float* outhA  = g_h  + b0 * TP1 * 32;  float* outhB  = g_h  + b1 * TP1 * 32;

    __syncthreads();

    float pxA = prex_sh[ev_sh[0][0] * H7 + j];
    float pxB = prex_sh[ev_sh[1][0] * H7 + j];

    for (int t = 0; t < TP1; t++) {
        // ---------- phase 1: two packed dots + uniform activation ----------
        unsigned long long accA[4] = {0,0,0,0}, accB[4] = {0,0,0,0};
        #pragma unroll
        for (int k = 0; k < 16; k++) {
            unsigned long long hA, hB;
            asm volatile("ld.shared.b64 %0,[%1];" : "=l"(hA) : "r"(hbA + k * 8));
            asm volatile("ld.shared.b64 %0,[%1];" : "=l"(hB) : "r"(hbB + k * 8));
            asm volatile("fma.rn.f32x2 %0,%1,%2,%0;" : "+l"(accA[k & 3]) : "l"(hA), "l"(wp[k]));
            asm volatile("fma.rn.f32x2 %0,%1,%2,%0;" : "+l"(accB[k & 3]) : "l"(hB), "l"(wp[k]));
        }
        asm("add.rn.f32x2 %0,%0,%1;" : "+l"(accA[0]) : "l"(accA[1]));
        asm("add.rn.f32x2 %0,%0,%1;" : "+l"(accA[2]) : "l"(accA[3]));
        asm("add.rn.f32x2 %0,%0,%1;" : "+l"(accA[0]) : "l"(accA[2]));
        asm("add.rn.f32x2 %0,%0,%1;" : "+l"(accB[0]) : "l"(accB[1]));
        asm("add.rn.f32x2 %0,%0,%1;" : "+l"(accB[2]) : "l"(accB[3]));
        asm("add.rn.f32x2 %0,%0,%1;" : "+l"(accB[0]) : "l"(accB[2]));
        float loA, hiA, loB, hiB;
        asm("mov.b64 {%0,%1},%2;" : "=f"(loA), "=f"(hiA) : "l"(accA[0]));
        asm("mov.b64 {%0,%1},%2;" : "=f"(loB), "=f"(hiB) : "l"(accB[0]));
        float preA = pxA + loA + hiA;
        float preB = pxB + loB + hiB;

        float aA, aB;
        if (w == 2) {                       // z: tanh  (uniform per warp)
            aA = tanh_fast(preA); aB = tanh_fast(preB);
        } else if (w == 6) {                // delta: softplus in log2 domain
            aA = softplus_log2(preA); aB = softplus_log2(preB);
            e_sh[0][lane] = ex2f(-aA * dt_sh[0][t + 1]);
            e_sh[1][lane] = ex2f(-aB * dt_sh[1][t + 1]);
            outdA[t * 32 + lane] = aA;
            outdB[t * 32 + lane] = aB;
        } else {                            // i,f,o,ib,fb: sigmoid
            aA = sig_fast(preA); aB = sig_fast(preB);
            if (w == 3) {                   // o gate also goes to global
                outoA[t * 32 + lane] = aA;
                outoB[t * 32 + lane] = aB;
            }
        }
        act[0][j] = aA;
        act[1][j] = aB;

        // prefetch next step's pre-x (hidden under barrier + phase 2)
        if (t + 1 < TP1) {
            pxA = prex_sh[ev_sh[0][t + 1] * H7 + j];
            pxB = prex_sh[ev_sh[1][t + 1] * H7 + j];
        }
        __syncthreads();

        // ---------- phase 2: warp0 -> batch A, warp1 -> batch B ------------
        if (w < 2) {
            const float* A = act[w];
            float iv  = A[lane];
            float fv  = A[32  + lane];
            float zv  = A[64  + lane];
            float ov  = A[96  + lane];
            float ibv = A[128 + lane];
            float fbv = A[160 + lane];
            float e   = e_sh[w][lane];

            float c  = fmaf(fv,  cm,  iv  * zv);
            float cbv= fmaf(fbv, cbm, ibv * zv);
            float cn = fmaf(c - cbv, e, cbv);
            float h  = ov * tanh_fast(cn);

            int base = t * 32 + lane;
            if (w == 0) { outcA[base] = c; outcbA[base] = cbv; outhA[base] = h; }
            else        { outcB[base] = c; outcbB[base] = cbv; outhB[base] = h; }

            ((float*)h2s)[32 * w + lane] = h;
            cm = cn; cbm = cbv;
        }
        __syncthreads();
    }
}

// ---------------- kernel C: MC sampling + lambda_sample + integral ---------
__global__ void __launch_bounds__(256)
k_sample(const float* __restrict__ dts,
         const float* __restrict__ mask,
         const float* __restrict__ dur,
         const float* __restrict__ Wl,
         float* __restrict__ lam_out) {
    const int b    = blockIdx.x;
    const int tid  = threadIdx.x;
    const int lane = tid & 31;
    const int wid  = tid >> 5;

    __shared__ float sh_ch[8][32];
    __shared__ float red[8];

    float wle[32];
    const float4* wl4 = (const float4*)(Wl + lane * 32);
    #pragma unroll
    for (int p = 0; p < 8; p++) {
        float4 wv = wl4[p];
        wle[4 * p + 0] = wv.x; wle[4 * p + 1] = wv.y;
        wle[4 * p + 2] = wv.z; wle[4 * p + 3] = wv.w;
    }

    float accLam = 0.0f, accMask = 0.0f;

    for (int s = wid; s < SSV; s += 8) {
        int r    = b * SSV + s;
        int base = r * 32;

        float cv  = g_c [base + lane];
        float cbv = g_cb[base + lane];
        float dv  = g_d [base + lane];    // log2-domain delta
        float ov  = g_o [base + lane];
        float dtv = dts[r];

        float cd  = fmaf(cv - cbv, ex2f(-dv * dtv), cbv);
        float chv = ov * tanh_fast(cd);
        sh_ch[wid][lane] = chv;
        __syncwarp();

        float d0 = 0.f, d1 = 0.f, d2 = 0.f, d3 = 0.f;
        const float4* ch4 = (const float4*)sh_ch[wid];
        #pragma unroll
        for (int p = 0; p < 8; p++) {
            float4 c4 = ch4[p];
            d0 = fmaf(c4.x, wle[4 * p + 0], d0);
            d1 = fmaf(c4.y, wle[4 * p + 1], d1);
            d2 = fmaf(c4.z, wle[4 * p + 2], d2);
            d3 = fmaf(c4.w, wle[4 * p + 3], d3);
        }
        float sp = softplus_fast((d0 + d1) + (d2 + d3));
        lam_out[(size_t)r * 32 + lane] = sp;

        float m = mask[r];
        accLam += sp * m;
        if (lane == 0) accMask += m;
        __syncwarp();
    }

    float sLam = block_reduce(accLam, red);
    __syncthreads();
    float sMask = block_reduce(accMask, red);
    if (tid == 0) g_integ[b] = __fdividef(sLam, sMask) * dur[b];
}

// ---------------- kernel D: target log-lambda ------------------------------
__global__ void __launch_bounds__(256)
k_target(const int* __restrict__ event,
         const float* __restrict__ Wl) {
    const int b   = blockIdx.x;
    const int tid = threadIdx.x;

    __shared__ float wl[32 * 33];              // stride 33: conflict-free
    __shared__ float red[8];
    for (int i = tid; i < 1024; i += 256)
        wl[(i >> 5) * 33 + (i & 31)] = Wl[i];
    __syncthreads();

    const int* evrow = event + b * T2V;
    float accL = 0.0f, accN = 0.0f;

    for (int t = tid; t < TP1; t += 256) {
        int tgt = evrow[t + 1];
        bool m  = (tgt < 32);
        int tt  = m ? tgt : 0;

        const float4* h4 = (const float4*)(g_h + (b * TP1 + t) * 32);
        const float* wr  = wl + tt * 33;
        float d0 = 0.f, d1 = 0.f, d2 = 0.f, d3 = 0.f;
        #pragma unroll
        for (int p = 0; p < 8; p++) {
            float4 hv = h4[p];
            d0 = fmaf(hv.x, wr[4 * p + 0], d0);
            d1 = fmaf(hv.y, wr[4 * p + 1], d1);
            d2 = fmaf(hv.z, wr[4 * p + 2], d2);
            d3 = fmaf(hv.w, wr[4 * p + 3], d3);
        }
        float lam = softplus_fast((d0 + d1) + (d2 + d3));
        if (m) { accL += lg2f(lam + EPSV) * LN2; accN += 1.0f; }
    }

    float sL = block_reduce(accL, red);
    __syncthreads();
    float sN = block_reduce(accN, red);
    if (tid == 0) { g_loglam[b] = sL; g_nev[b] = sN; }
}

// ---------------- kernel E: final scalars ----------------------------------
__global__ void __launch_bounds__(256)
k_final(float* __restrict__ out) {
    const int tid = threadIdx.x;
    __shared__ float red[8];
    float lp = g_loglam[tid] - g_integ[tid];
    float nv = g_nev[tid];
    float sLP = block_reduce(lp, red);
    __syncthreads();
    float sNV = block_reduce(nv, red);
    if (tid == 0) {
        out[0] = -sLP;
        out[1] = sNV;
    }
}

// ---------------- launch ----------------
extern "C" void kernel_launch(void* const* d_in, const int* in_sizes, int n_in,
                              void* d_out, int out_size) {
    const int*   event = (const int*)  d_in[0];
    const float* dtime = (const float*)d_in[1];
    const float* dur   = (const float*)d_in[2];
    const float* dts   = (const float*)d_in[3];
    // d_in[4] = index_of_hidden_sampling (unused by the reference)
    const float* mask  = (const float*)d_in[5];
    const float* Emb   = (const float*)d_in[6];
    const float* W     = (const float*)d_in[7];
    const float* bias  = (const float*)d_in[8];
    const float* Wl    = (const float*)d_in[9];

    float* out = (float*)d_out;
    long long lam_elems = (long long)HN * 32;
    long long lamoff = (long long)out_size - lam_elems;
    if (lamoff < 0) lamoff = 0;
    float* lam_out = out + lamoff;

    k_prex  <<<NVOC, H7>>>(Emb, W, bias);
    k_scan  <<<BB / 2, H7>>>(event, dtime, W);
    k_sample<<<BB, 256>>>(dts, mask, dur, Wl, lam_out);
    k_target<<<BB, 256>>>(event, Wl);
    k_final <<<1, 256>>>(out);
}